// round 16
// baseline (speedup 1.0000x reference)
#include <cuda_runtime.h>

// ParametricInterpolation — numerics FROZEN (bit-exact vs reference since R8):
//   p_k = RN(params_k * RN(1/fl32(scaler_k)))   (XLA divide->recip-mul)
//   i2 = RN(i*i), i3 = RN(i2*i), i4 = RN(i2*i2) (integer_pow sq-and-mul)
//   c  = RN(p0*i4); fma(p1,i3); fma(p2,i2); fma(p3,i); + p4  (ascending fma)
//   round-half-even (magic 2^23+2^22, == rintf for |c| < 2^22)
//   k = RN(c - ci); pos = clip(n - ci, 1, 2047)
//   out = RN(RN(x1*RN(1-k)) + RN(x2*k))          (non-contracted lerp)
//
// R16: curve math runs on Blackwell f32x2 packed ops (mul/add/fma.rn.f32x2,
// PTX-only; each lane is an independent IEEE-RN fp32 op => bit-identical to
// the scalar chain). 8 parts -> 4 pairs: ~15% fewer issued instructions and
// 2x FFMA work per issue slot. Early gather issue + __stcs stores kept (R15).

#define SIG_LEN 2048
#define PAIRS   4                 // 8 parts, 2 per packed lane-pair
#define MAGIC_F 12582912.0f       // 2^23 + 2^22
#define MAGIC_I 0x4B400000

typedef unsigned long long u64;

__device__ __forceinline__ u64 pack2(float lo, float hi) {
    u64 r; asm("mov.b64 %0, {%1, %2};" : "=l"(r) : "f"(lo), "f"(hi)); return r;
}
__device__ __forceinline__ void unpack2(u64 v, float& lo, float& hi) {
    asm("mov.b64 {%0, %1}, %2;" : "=f"(lo), "=f"(hi) : "l"(v));
}
__device__ __forceinline__ u64 mul2(u64 a, u64 b) {
    u64 d; asm("mul.rn.f32x2 %0, %1, %2;" : "=l"(d) : "l"(a), "l"(b)); return d;
}
__device__ __forceinline__ u64 add2(u64 a, u64 b) {
    u64 d; asm("add.rn.f32x2 %0, %1, %2;" : "=l"(d) : "l"(a), "l"(b)); return d;
}
__device__ __forceinline__ u64 fma2(u64 a, u64 b, u64 c) {
    u64 d; asm("fma.rn.f32x2 %0, %1, %2, %3;" : "=l"(d) : "l"(a), "l"(b), "l"(c)); return d;
}

__global__ __launch_bounds__(256, 7)
void pik_kernel(const float* __restrict__ x,
                const float* __restrict__ params,
                float* __restrict__ out)
{
    const int b   = blockIdx.x;
    const int tid = threadIdx.x;

    // Warp-uniform param loads -> broadcast, L1-resident.
    const float* pb = params + (size_t)b * 5;
    const float p0 = __fmul_rn(__ldg(pb + 0), (float)(1.0 / (double)1e12f));
    const float p1 = __fmul_rn(__ldg(pb + 1), (float)(1.0 / (double)1e8f));
    const float p2 = __fmul_rn(__ldg(pb + 2), (float)(1.0 / (double)1e4f));
    const float p3 =            __ldg(pb + 3);   // inv = 1.0 exactly
    const float p4 = __fmul_rn(__ldg(pb + 4), (float)(1.0 / (double)10.0f));

    const u64 p0x = pack2(p0, p0), p1x = pack2(p1, p1), p2x = pack2(p2, p2),
              p3x = pack2(p3, p3), p4x = pack2(p4, p4);
    const u64 magic2 = pack2(MAGIC_F, MAGIC_F);
    const u64 nmag2  = pack2(-MAGIC_F, -MAGIC_F);
    const u64 none2  = pack2(-1.0f, -1.0f);

    const float* xrow = x   + (size_t)b * SIG_LEN;
    float*       orow = out + (size_t)b * SIG_LEN;

    const float fi0 = (float)tid;   // single I2F per thread

    u64   kk2[PAIRS];
    float x1v[2 * PAIRS], x2v[2 * PAIRS];

    // Phase 1: packed curve for part-pairs (2q, 2q+1); gathers issue per pair.
    #pragma unroll
    for (int q = 0; q < PAIRS; ++q) {
        const int   na = q * 512 + tid;               // n of part 2q
        const float fa = fi0 + (float)(q * 512);      // exact
        const float fb = fa + 256.0f;                 // exact

        const u64 fi2 = pack2(fa, fb);
        const u64 i2  = mul2(fi2, fi2);               // exact per lane
        const u64 i3  = mul2(i2, fi2);
        const u64 i4  = mul2(i2, i2);

        u64 c = mul2(p0x, i4);                        // ascending-k fma chain
        c = fma2(p1x, i3, c);
        c = fma2(p2x, i2, c);
        c = fma2(p3x, fi2, c);
        c = add2(c, p4x);

        const u64 y  = add2(c, magic2);               // round half to even
        const u64 ci = add2(y, nmag2);                // exact
        kk2[q] = fma2(ci, none2, c);                  // k = RN(c - ci), bit-exact

        float ya, yb; unpack2(y, ya, yb);
        const int cia = __float_as_int(ya) - MAGIC_I;
        const int cib = __float_as_int(yb) - MAGIC_I;

        int pa = na - cia;        pa = max(1, min(SIG_LEN - 1, pa));
        int pbi = na + 256 - cib; pbi = max(1, min(SIG_LEN - 1, pbi));

        x1v[2 * q]     = __ldg(xrow + pa);            // issue now
        x2v[2 * q]     = __ldg(xrow + pa - 1);
        x1v[2 * q + 1] = __ldg(xrow + pbi);
        x2v[2 * q + 1] = __ldg(xrow + pbi - 1);
    }

    // Phase 2: unpack k, scalar non-contracted lerp, streaming stores.
    #pragma unroll
    for (int q = 0; q < PAIRS; ++q) {
        float ka, kb; unpack2(kk2[q], ka, kb);

        const float w1a = __fsub_rn(1.0f, ka);
        const float va  = __fadd_rn(__fmul_rn(x1v[2 * q], w1a),
                                    __fmul_rn(x2v[2 * q], ka));
        __stcs(orow + q * 512 + tid, va);

        const float w1b = __fsub_rn(1.0f, kb);
        const float vb  = __fadd_rn(__fmul_rn(x1v[2 * q + 1], w1b),
                                    __fmul_rn(x2v[2 * q + 1], kb));
        __stcs(orow + q * 512 + 256 + tid, vb);
    }
}

extern "C" void kernel_launch(void* const* d_in, const int* in_sizes, int n_in,
                              void* d_out, int out_size)
{
    const float* x;
    const float* params;
    if (n_in >= 2 && in_sizes[0] < in_sizes[1]) {
        params = (const float*)d_in[0];
        x      = (const float*)d_in[1];
    } else {
        x      = (const float*)d_in[0];
        params = (const float*)d_in[1];
    }
    float* out = (float*)d_out;

    const int batch = 16384;
    pik_kernel<<<batch, 256>>>(x, params, out);
}